// round 4
// baseline (speedup 1.0000x reference)
#include <cuda_runtime.h>
#include <math.h>

#define HH 256
#define WW 256
#define HW 65536
#define NB 8
#define NSLICE 24      // NB * 3 kept channels
#define NPIX (NB*HW)   // 524288
#define CAP 512        // INF = H + W in reference
#define BIG (1<<20)

// -------- device scratch (no allocations allowed) --------
__device__ uchar4   g_masks4[NPIX / 4];          // per-pixel: bits 0..2 mask_p cc, 3..5 mask_t cc
__device__ float4   g_p4[NSLICE * HW / 4];       // softmax probs, channels 1..3
__device__ unsigned g_bits[2 * NSLICE * 8 * WW]; // column-packed bits [plane][slice][word][col]
__device__ int      g_cnt[2 * NSLICE];           // [0..23] p-counts, [24..47] t-counts
__device__ double   g_acc;

// -------- kernel 0: zero accumulators --------
__global__ void k_init() {
    int t = threadIdx.x;
    if (t < 2 * NSLICE) g_cnt[t] = 0;
    if (t == 0) g_acc = 0.0;
}

// per-pixel softmax(4) + argmax(4) -> probs of ch 1..3 + 6 mask bits
__device__ __forceinline__ void pixel_work(float s0, float s1, float s2, float s3,
                                           float t0, float t1, float t2, float t3,
                                           float& p1, float& p2, float& p3,
                                           unsigned& mk) {
    float m  = fmaxf(fmaxf(s0, s1), fmaxf(s2, s3));
    float e0 = __expf(s0 - m), e1 = __expf(s1 - m), e2 = __expf(s2 - m), e3 = __expf(s3 - m);
    float inv = 1.0f / (e0 + e1 + e2 + e3);
    p1 = e1 * inv; p2 = e2 * inv; p3 = e3 * inv;

    int lab = 0; float best = t0;            // first-index-wins (matches jnp.argmax)
    if (t1 > best) { best = t1; lab = 1; }
    if (t2 > best) { best = t2; lab = 2; }
    if (t3 > best) { best = t3; lab = 3; }

    mk = 0;
    if (p1 > 0.5f) mk |= 1u;
    if (p2 > 0.5f) mk |= 2u;
    if (p3 > 0.5f) mk |= 4u;
    if (lab == 1)  mk |= 8u;
    if (lab == 2)  mk |= 16u;
    if (lab == 3)  mk |= 32u;
}

// -------- kernel 1: softmax + argmax + masks (4 px/thread) --------
__global__ void __launch_bounds__(256) k_prep(const float4* __restrict__ S4,
                                              const float4* __restrict__ T4) {
    int q  = blockIdx.x * 256 + threadIdx.x;   // quad index
    int b  = q >> 14;                          // 16384 quads per image
    int pq = q & 16383;

    const float4* s = S4 + (size_t)b * 4 * 16384 + pq;
    float4 s0 = s[0], s1 = s[16384], s2 = s[2 * 16384], s3 = s[3 * 16384];
    const float4* t = T4 + (size_t)b * 4 * 16384 + pq;
    float4 t0 = t[0], t1 = t[16384], t2 = t[2 * 16384], t3 = t[3 * 16384];

    float4 P1, P2, P3;
    unsigned m0, m1, m2, m3;
    pixel_work(s0.x, s1.x, s2.x, s3.x, t0.x, t1.x, t2.x, t3.x, P1.x, P2.x, P3.x, m0);
    pixel_work(s0.y, s1.y, s2.y, s3.y, t0.y, t1.y, t2.y, t3.y, P1.y, P2.y, P3.y, m1);
    pixel_work(s0.z, s1.z, s2.z, s3.z, t0.z, t1.z, t2.z, t3.z, P1.z, P2.z, P3.z, m2);
    pixel_work(s0.w, s1.w, s2.w, s3.w, t0.w, t1.w, t2.w, t3.w, P1.w, P2.w, P3.w, m3);

    g_masks4[q] = make_uchar4((unsigned char)m0, (unsigned char)m1,
                              (unsigned char)m2, (unsigned char)m3);
    int base = (b * 3) * 16384 + pq;
    g_p4[base]             = P1;
    g_p4[base + 16384]     = P2;
    g_p4[base + 2 * 16384] = P3;
}

// -------- kernel 2: transpose masks into column-packed bit planes + counts --------
__global__ void __launch_bounds__(256) k_pack() {
    int b = blockIdx.x >> 3;
    int w = blockIdx.x & 7;
    int j = threadIdx.x;

    const unsigned char* mk = ((const unsigned char*)g_masks4) + (size_t)b * HW + j;
    unsigned wd[6] = {0, 0, 0, 0, 0, 0};
    #pragma unroll 8
    for (int i2 = 0; i2 < 32; i2++) {
        unsigned m = mk[(w * 32 + i2) * WW];
        #pragma unroll
        for (int bit = 0; bit < 6; bit++)
            wd[bit] |= ((m >> bit) & 1u) << i2;
    }
    #pragma unroll
    for (int cc = 0; cc < 3; cc++) {
        int s = b * 3 + cc;
        g_bits[(0 * NSLICE + s) * 8 * WW + w * WW + j] = wd[cc];       // p-plane
        g_bits[(1 * NSLICE + s) * 8 * WW + w * WW + j] = wd[3 + cc];   // t-plane
    }

    __shared__ int scnt[6];
    if (threadIdx.x < 6) scnt[threadIdx.x] = 0;
    __syncthreads();
    #pragma unroll
    for (int bit = 0; bit < 6; bit++) {
        int tot = __reduce_add_sync(0xffffffffu, __popc(wd[bit]));
        if ((threadIdx.x & 31) == 0) atomicAdd(&scnt[bit], tot);
    }
    __syncthreads();
    if (threadIdx.x < 3)      atomicAdd(&g_cnt[b * 3 + threadIdx.x], scnt[threadIdx.x]);
    else if (threadIdx.x < 6) atomicAdd(&g_cnt[NSLICE + b * 3 + threadIdx.x - 3], scnt[threadIdx.x]);
}

// exact outward search: min_k G[k] + (j-k)^2, early exit when d*d >= best
__device__ __forceinline__ int edt_search(const int* __restrict__ G, int j) {
    int best = G[j];
    #pragma unroll 4
    for (int d = 1; d < WW; d++) {
        int dd = d * d;
        if (dd >= best) break;
        int jm = j - d, jp = j + d;
        if (jm >= 0) best = min(best, G[jm] + dd);
        if (jp < WW) best = min(best, G[jp] + dd);
    }
    return best;
}

// band-boundary fallbacks for one plane held in registers (macro keeps reg array)
#define FALLBACKS(W8, WB, CUR, FB0, FB1, LA0, LA1)                         \
    {                                                                      \
        FB0 = BIG; FB1 = BIG; LA0 = -BIG; LA1 = -BIG; CUR = 0;             \
        _Pragma("unroll")                                                  \
        for (int w = 0; w < 8; w++) {                                      \
            unsigned z = ~W8[w], o = W8[w];                                \
            if (w == WB) CUR = W8[w];                                      \
            if (w > WB) {                                                  \
                if (z && FB0 == BIG) FB0 = w * 32 + __ffs(z) - 1;          \
                if (o && FB1 == BIG) FB1 = w * 32 + __ffs(o) - 1;          \
            } else if (w < WB) {                                           \
                if (z) LA0 = w * 32 + 31 - __clz(z);                       \
                if (o) LA1 = w * 32 + 31 - __clz(o);                       \
            }                                                              \
        }                                                                  \
    }

// per-row vertical distances (to nearest clear bit d0, nearest set bit d1)
__device__ __forceinline__ void vrow(unsigned cur, int r, int R,
                                     int fb0, int fb1, int la0, int la1,
                                     int& d0, int& d1) {
    unsigned hi = 0xFFFFFFFFu << r;
    unsigned lo = 0xFFFFFFFFu >> (31 - r);
    unsigned nc = ~cur;

    unsigned x0 = nc & hi;
    int dn0 = x0 ? (__ffs(x0) - 1 - r) : (fb0 - R);
    unsigned y0 = nc & lo;
    int up0 = y0 ? (r - (31 - __clz(y0))) : (R - la0);
    d0 = min(min(dn0, up0), CAP);

    unsigned x1 = cur & hi;
    int dn1 = x1 ? (__ffs(x1) - 1 - r) : (fb1 - R);
    unsigned y1 = cur & lo;
    int up1 = y1 ? (r - (31 - __clz(y1))) : (R - la1);
    d1 = min(min(dn1, up1), CAP);
}

// -------- kernel 3: banded fused vertical+horizontal EDT + loss --------
// block = (slice, 32-row band); thread = column; grid = 24*8 = 192
__global__ void __launch_bounds__(256) k_main() {
    int s  = blockIdx.x >> 3;      // slice 0..23
    int wb = blockIdx.x & 7;       // band / word index
    int j  = threadIdx.x;          // column

    const unsigned* Pp = g_bits + (size_t)(0 * NSLICE + s) * 8 * WW;
    const unsigned* Pt = g_bits + (size_t)(1 * NSLICE + s) * 8 * WW;

    unsigned wp[8], wt[8];
    #pragma unroll
    for (int w = 0; w < 8; w++) { wp[w] = Pp[w * WW + j]; wt[w] = Pt[w * WW + j]; }

    unsigned curp, curt;
    int fb0p, fb1p, la0p, la1p, fb0t, fb1t, la0t, la1t;
    FALLBACKS(wp, wb, curp, fb0p, fb1p, la0p, la1p)
    FALLBACKS(wt, wb, curt, fb0t, fb1t, la0t, la1t)

    int cp = g_cnt[s], ct = g_cnt[NSLICE + s];
    float vp = (cp > 0 && cp < HW) ? 1.0f : 0.0f;
    float vt = (ct > 0 && ct < HW) ? 1.0f : 0.0f;

    __shared__ int G[2][4][WW];    // double-buffered per row
    const float* prow = ((const float*)g_p4) + (size_t)s * HW + (size_t)wb * 32 * WW + j;

    float acc = 0.0f;
    #pragma unroll 4
    for (int r = 0; r < 32; r++) {
        int R = wb * 32 + r;
        int d0, d1;
        int* Ga = &G[r & 1][0][0];
        vrow(curp, r, R, fb0p, fb1p, la0p, la1p, d0, d1);
        Ga[0 * WW + j] = d0 * d0;
        Ga[1 * WW + j] = d1 * d1;
        vrow(curt, r, R, fb0t, fb1t, la0t, la1t, d0, d1);
        Ga[2 * WW + j] = d0 * d0;
        Ga[3 * WW + j] = d1 * d1;
        __syncthreads();

        int p_true = (curp >> r) & 1;
        int t_true = (curt >> r) & 1;
        int dp = edt_search(Ga + (p_true ? 0 : 1) * WW, j);
        int dt = edt_search(Ga + (t_true ? 2 : 3) * WW, j);

        float p   = prow[r * WW];
        float err = (p - (float)t_true) * (p - (float)t_true);
        acc += err * ((float)dp * vp + (float)dt * vt);
    }

    // block reduction -> double atomic (once per block)
    #pragma unroll
    for (int o = 16; o; o >>= 1) acc += __shfl_down_sync(0xffffffffu, acc, o);
    __shared__ float wsum[8];
    if ((threadIdx.x & 31) == 0) wsum[threadIdx.x >> 5] = acc;
    __syncthreads();
    if (threadIdx.x == 0) {
        float ssum = 0.0f;
        #pragma unroll
        for (int w = 0; w < 8; w++) ssum += wsum[w];
        atomicAdd(&g_acc, (double)ssum);
    }
}

// -------- kernel 4: finalize --------
__global__ void k_final(float* out) {
    double mean = g_acc / (double)(NSLICE * HW);
    out[0] = (float)log(mean + 1.0);
}

extern "C" void kernel_launch(void* const* d_in, const int* in_sizes, int n_in,
                              void* d_out, int out_size) {
    const float4* S = (const float4*)d_in[0];   // preds_S (8,4,256,256)
    const float4* T = (const float4*)d_in[1];   // preds_T (8,4,256,256)
    (void)in_sizes; (void)n_in; (void)out_size; // target (d_in[2]) unused by reference

    k_init<<<1, 64>>>();
    k_prep<<<NPIX / 4 / 256, 256>>>(S, T);
    k_pack<<<64, 256>>>();
    k_main<<<NSLICE * 8, 256>>>();
    k_final<<<1, 1>>>((float*)d_out);
}

// round 5
// speedup vs baseline: 1.2797x; 1.2797x over previous
#include <cuda_runtime.h>
#include <math.h>

#define HH 256
#define WW 256
#define HW 65536
#define NB 8
#define NSLICE 24      // NB * 3 kept channels
#define NPIX (NB*HW)   // 524288
#define CAP 512        // INF = H + W in reference
#define BIG (1<<20)
#define RPB 8          // rows per block in k_main

// -------- device scratch (no allocations allowed) --------
__device__ uchar4   g_masks4[NPIX / 4];          // per-pixel: bits 0..2 mask_p cc, 3..5 mask_t cc
__device__ float4   g_p4[NSLICE * HW / 4];       // softmax probs, channels 1..3
__device__ unsigned g_bits[2 * NSLICE * 8 * WW]; // column-packed bits [plane][slice][word][col]
__device__ int      g_cnt[2 * NSLICE];           // [0..23] p-counts, [24..47] t-counts
__device__ double   g_acc;

// -------- kernel 0: zero accumulators --------
__global__ void k_init() {
    int t = threadIdx.x;
    if (t < 2 * NSLICE) g_cnt[t] = 0;
    if (t == 0) g_acc = 0.0;
}

// per-pixel softmax(4) + argmax(4) -> probs of ch 1..3 + 6 mask bits
__device__ __forceinline__ void pixel_work(float s0, float s1, float s2, float s3,
                                           float t0, float t1, float t2, float t3,
                                           float& p1, float& p2, float& p3,
                                           unsigned& mk) {
    float m  = fmaxf(fmaxf(s0, s1), fmaxf(s2, s3));
    float e0 = __expf(s0 - m), e1 = __expf(s1 - m), e2 = __expf(s2 - m), e3 = __expf(s3 - m);
    float inv = 1.0f / (e0 + e1 + e2 + e3);
    p1 = e1 * inv; p2 = e2 * inv; p3 = e3 * inv;

    int lab = 0; float best = t0;            // first-index-wins (matches jnp.argmax)
    if (t1 > best) { best = t1; lab = 1; }
    if (t2 > best) { best = t2; lab = 2; }
    if (t3 > best) { best = t3; lab = 3; }

    mk = 0;
    if (p1 > 0.5f) mk |= 1u;
    if (p2 > 0.5f) mk |= 2u;
    if (p3 > 0.5f) mk |= 4u;
    if (lab == 1)  mk |= 8u;
    if (lab == 2)  mk |= 16u;
    if (lab == 3)  mk |= 32u;
}

// -------- kernel 1: softmax + argmax + masks (4 px/thread) --------
__global__ void __launch_bounds__(256) k_prep(const float4* __restrict__ S4,
                                              const float4* __restrict__ T4) {
    int q  = blockIdx.x * 256 + threadIdx.x;   // quad index
    int b  = q >> 14;                          // 16384 quads per image
    int pq = q & 16383;

    const float4* s = S4 + (size_t)b * 4 * 16384 + pq;
    float4 s0 = s[0], s1 = s[16384], s2 = s[2 * 16384], s3 = s[3 * 16384];
    const float4* t = T4 + (size_t)b * 4 * 16384 + pq;
    float4 t0 = t[0], t1 = t[16384], t2 = t[2 * 16384], t3 = t[3 * 16384];

    float4 P1, P2, P3;
    unsigned m0, m1, m2, m3;
    pixel_work(s0.x, s1.x, s2.x, s3.x, t0.x, t1.x, t2.x, t3.x, P1.x, P2.x, P3.x, m0);
    pixel_work(s0.y, s1.y, s2.y, s3.y, t0.y, t1.y, t2.y, t3.y, P1.y, P2.y, P3.y, m1);
    pixel_work(s0.z, s1.z, s2.z, s3.z, t0.z, t1.z, t2.z, t3.z, P1.z, P2.z, P3.z, m2);
    pixel_work(s0.w, s1.w, s2.w, s3.w, t0.w, t1.w, t2.w, t3.w, P1.w, P2.w, P3.w, m3);

    g_masks4[q] = make_uchar4((unsigned char)m0, (unsigned char)m1,
                              (unsigned char)m2, (unsigned char)m3);
    int base = (b * 3) * 16384 + pq;
    g_p4[base]             = P1;
    g_p4[base + 16384]     = P2;
    g_p4[base + 2 * 16384] = P3;
}

// -------- kernel 2: transpose masks into column-packed bit planes + counts --------
__global__ void __launch_bounds__(256) k_pack() {
    int b = blockIdx.x >> 3;
    int w = blockIdx.x & 7;
    int j = threadIdx.x;

    const unsigned char* mk = ((const unsigned char*)g_masks4) + (size_t)b * HW + j;
    unsigned wd[6] = {0, 0, 0, 0, 0, 0};
    #pragma unroll 8
    for (int i2 = 0; i2 < 32; i2++) {
        unsigned m = mk[(w * 32 + i2) * WW];
        #pragma unroll
        for (int bit = 0; bit < 6; bit++)
            wd[bit] |= ((m >> bit) & 1u) << i2;
    }
    #pragma unroll
    for (int cc = 0; cc < 3; cc++) {
        int s = b * 3 + cc;
        g_bits[(0 * NSLICE + s) * 8 * WW + w * WW + j] = wd[cc];       // p-plane
        g_bits[(1 * NSLICE + s) * 8 * WW + w * WW + j] = wd[3 + cc];   // t-plane
    }

    __shared__ int scnt[6];
    if (threadIdx.x < 6) scnt[threadIdx.x] = 0;
    __syncthreads();
    #pragma unroll
    for (int bit = 0; bit < 6; bit++) {
        int tot = __reduce_add_sync(0xffffffffu, __popc(wd[bit]));
        if ((threadIdx.x & 31) == 0) atomicAdd(&scnt[bit], tot);
    }
    __syncthreads();
    if (threadIdx.x < 3)      atomicAdd(&g_cnt[b * 3 + threadIdx.x], scnt[threadIdx.x]);
    else if (threadIdx.x < 6) atomicAdd(&g_cnt[NSLICE + b * 3 + threadIdx.x - 3], scnt[threadIdx.x]);
}

// exact outward search: min_k G[k] + (j-k)^2, early exit when d*d >= best
__device__ __forceinline__ int edt_search(const int* __restrict__ G, int j) {
    int best = G[j];
    #pragma unroll 4
    for (int d = 1; d < WW; d++) {
        int dd = d * d;
        if (dd >= best) break;
        int jm = j - d, jp = j + d;
        if (jm >= 0) best = min(best, G[jm] + dd);
        if (jp < WW) best = min(best, G[jp] + dd);
    }
    return best;
}

// on-demand out-of-word fallbacks for one plane/column (early-break; usually 1 iter)
__device__ __forceinline__ void fallbacks(const unsigned* __restrict__ P, int j, int w0,
                                          int& fb0, int& fb1, int& la0, int& la1) {
    fb0 = BIG; fb1 = BIG;
    for (int w = w0 + 1; w < 8 && (fb0 == BIG || fb1 == BIG); w++) {
        unsigned ww = P[w * WW + j];
        if (fb0 == BIG && ~ww) fb0 = w * 32 + __ffs(~ww) - 1;
        if (fb1 == BIG &&  ww) fb1 = w * 32 + __ffs(ww) - 1;
    }
    la0 = -BIG; la1 = -BIG;
    for (int w = w0 - 1; w >= 0 && (la0 == -BIG || la1 == -BIG); w--) {
        unsigned ww = P[w * WW + j];
        if (la0 == -BIG && ~ww) la0 = w * 32 + 31 - __clz(~ww);
        if (la1 == -BIG &&  ww) la1 = w * 32 + 31 - __clz(ww);
    }
}

// per-row vertical distances from register word + precomputed fallbacks
__device__ __forceinline__ void vrow(unsigned cur, int br, int R,
                                     int fb0, int fb1, int la0, int la1,
                                     int& d0, int& d1) {
    unsigned hi = 0xFFFFFFFFu << br;
    unsigned lo = 0xFFFFFFFFu >> (31 - br);
    unsigned nc = ~cur;

    unsigned x0 = nc & hi;
    int dn0 = x0 ? (__ffs(x0) - 1 - br) : (fb0 - R);
    unsigned y0 = nc & lo;
    int up0 = y0 ? (br - (31 - __clz(y0))) : (R - la0);
    d0 = min(min(dn0, up0), CAP);

    unsigned x1 = cur & hi;
    int dn1 = x1 ? (__ffs(x1) - 1 - br) : (fb1 - R);
    unsigned y1 = cur & lo;
    int up1 = y1 ? (br - (31 - __clz(y1))) : (R - la1);
    d1 = min(min(dn1, up1), CAP);
}

// -------- kernel 3: fused vertical+horizontal EDT + loss, 8 rows/block --------
// block = (slice, 8-row band); grid = 24*32 = 768 (single wave)
__global__ void __launch_bounds__(256) k_main() {
    int s    = blockIdx.x >> 5;    // slice 0..23
    int band = blockIdx.x & 31;    // 8-row band 0..31
    int j    = threadIdx.x;        // column
    int w0   = band >> 2;          // word holding all 8 rows
    int bb   = (band & 3) * 8;     // bit base within word

    const unsigned* Pp = g_bits + (size_t)(0 * NSLICE + s) * 8 * WW;
    const unsigned* Pt = g_bits + (size_t)(1 * NSLICE + s) * 8 * WW;

    unsigned curp = Pp[w0 * WW + j];
    unsigned curt = Pt[w0 * WW + j];
    int fb0p, fb1p, la0p, la1p, fb0t, fb1t, la0t, la1t;
    fallbacks(Pp, j, w0, fb0p, fb1p, la0p, la1p);
    fallbacks(Pt, j, w0, fb0t, fb1t, la0t, la1t);

    __shared__ int G[RPB][4][WW];
    #pragma unroll
    for (int r = 0; r < RPB; r++) {
        int br = bb + r;
        int R  = band * RPB + r;
        int d0, d1;
        vrow(curp, br, R, fb0p, fb1p, la0p, la1p, d0, d1);
        G[r][0][j] = d0 * d0;
        G[r][1][j] = d1 * d1;
        vrow(curt, br, R, fb0t, fb1t, la0t, la1t, d0, d1);
        G[r][2][j] = d0 * d0;
        G[r][3][j] = d1 * d1;
    }
    __syncthreads();               // ONE barrier per block

    int cp = g_cnt[s], ct = g_cnt[NSLICE + s];
    float vp = (cp > 0 && cp < HW) ? 1.0f : 0.0f;
    float vt = (ct > 0 && ct < HW) ? 1.0f : 0.0f;

    const float* prow = ((const float*)g_p4) + (size_t)s * HW + (size_t)band * RPB * WW + j;

    float acc = 0.0f;
    #pragma unroll
    for (int r = 0; r < RPB; r++) {
        int br = bb + r;
        int p_true = (curp >> br) & 1;
        int t_true = (curt >> br) & 1;
        int dp = edt_search(&G[r][p_true ? 0 : 1][0], j);
        int dt = edt_search(&G[r][t_true ? 2 : 3][0], j);
        float p   = prow[r * WW];
        float err = (p - (float)t_true) * (p - (float)t_true);
        acc += err * ((float)dp * vp + (float)dt * vt);
    }

    // block reduction -> double atomic (once per block)
    #pragma unroll
    for (int o = 16; o; o >>= 1) acc += __shfl_down_sync(0xffffffffu, acc, o);
    __shared__ float wsum[8];
    if ((threadIdx.x & 31) == 0) wsum[threadIdx.x >> 5] = acc;
    __syncthreads();
    if (threadIdx.x == 0) {
        float ssum = 0.0f;
        #pragma unroll
        for (int w = 0; w < 8; w++) ssum += wsum[w];
        atomicAdd(&g_acc, (double)ssum);
    }
}

// -------- kernel 4: finalize --------
__global__ void k_final(float* out) {
    double mean = g_acc / (double)(NSLICE * HW);
    out[0] = (float)log(mean + 1.0);
}

extern "C" void kernel_launch(void* const* d_in, const int* in_sizes, int n_in,
                              void* d_out, int out_size) {
    const float4* S = (const float4*)d_in[0];   // preds_S (8,4,256,256)
    const float4* T = (const float4*)d_in[1];   // preds_T (8,4,256,256)
    (void)in_sizes; (void)n_in; (void)out_size; // target (d_in[2]) unused by reference

    k_init<<<1, 64>>>();
    k_prep<<<NPIX / 4 / 256, 256>>>(S, T);
    k_pack<<<64, 256>>>();
    k_main<<<NSLICE * 32, 256>>>();
    k_final<<<1, 1>>>((float*)d_out);
}

// round 6
// speedup vs baseline: 1.3738x; 1.0736x over previous
#include <cuda_runtime.h>
#include <math.h>

#define HH 256
#define WW 256
#define HW 65536
#define NB 8
#define NSLICE 24      // NB * 3 kept channels
#define NPIX (NB*HW)   // 524288
#define CAP 512        // INF = H + W in reference
#define BIG (1<<20)
#define RPB 4          // rows per block in k_main
#define NMAIN (NSLICE * (HH / RPB))   // 1536 blocks
#define WIN 5          // unconditional search window

// -------- device scratch (no allocations allowed) --------
__device__ uchar4   g_masks4[NPIX / 4];          // per-pixel: bits 0..2 mask_p cc, 3..5 mask_t cc
__device__ float4   g_p4[NSLICE * HW / 4];       // softmax probs, channels 1..3
__device__ unsigned g_bits[2 * NSLICE * 8 * WW]; // column-packed bits [plane][slice][word][col]
__device__ int      g_cnt[2 * NSLICE];           // [0..23] p-counts, [24..47] t-counts
__device__ double   g_acc;
__device__ int      g_done;

// per-pixel softmax(4) + argmax(4) -> probs of ch 1..3 + 6 mask bits
__device__ __forceinline__ void pixel_work(float s0, float s1, float s2, float s3,
                                           float t0, float t1, float t2, float t3,
                                           float& p1, float& p2, float& p3,
                                           unsigned& mk) {
    float m  = fmaxf(fmaxf(s0, s1), fmaxf(s2, s3));
    float e0 = __expf(s0 - m), e1 = __expf(s1 - m), e2 = __expf(s2 - m), e3 = __expf(s3 - m);
    float inv = 1.0f / (e0 + e1 + e2 + e3);
    p1 = e1 * inv; p2 = e2 * inv; p3 = e3 * inv;

    int lab = 0; float best = t0;            // first-index-wins (matches jnp.argmax)
    if (t1 > best) { best = t1; lab = 1; }
    if (t2 > best) { best = t2; lab = 2; }
    if (t3 > best) { best = t3; lab = 3; }

    mk = 0;
    if (p1 > 0.5f) mk |= 1u;
    if (p2 > 0.5f) mk |= 2u;
    if (p3 > 0.5f) mk |= 4u;
    if (lab == 1)  mk |= 8u;
    if (lab == 2)  mk |= 16u;
    if (lab == 3)  mk |= 32u;
}

// -------- kernel 1: softmax + argmax + masks (4 px/thread) + zero accumulators --------
__global__ void __launch_bounds__(256) k_prep(const float4* __restrict__ S4,
                                              const float4* __restrict__ T4) {
    if (blockIdx.x == 0) {                      // accumulators consumed only by LATER kernels
        if (threadIdx.x < 2 * NSLICE) g_cnt[threadIdx.x] = 0;
        if (threadIdx.x == 2 * NSLICE) { g_acc = 0.0; g_done = 0; }
    }

    int q  = blockIdx.x * 256 + threadIdx.x;   // quad index
    int b  = q >> 14;                          // 16384 quads per image
    int pq = q & 16383;

    const float4* s = S4 + (size_t)b * 4 * 16384 + pq;
    float4 s0 = s[0], s1 = s[16384], s2 = s[2 * 16384], s3 = s[3 * 16384];
    const float4* t = T4 + (size_t)b * 4 * 16384 + pq;
    float4 t0 = t[0], t1 = t[16384], t2 = t[2 * 16384], t3 = t[3 * 16384];

    float4 P1, P2, P3;
    unsigned m0, m1, m2, m3;
    pixel_work(s0.x, s1.x, s2.x, s3.x, t0.x, t1.x, t2.x, t3.x, P1.x, P2.x, P3.x, m0);
    pixel_work(s0.y, s1.y, s2.y, s3.y, t0.y, t1.y, t2.y, t3.y, P1.y, P2.y, P3.y, m1);
    pixel_work(s0.z, s1.z, s2.z, s3.z, t0.z, t1.z, t2.z, t3.z, P1.z, P2.z, P3.z, m2);
    pixel_work(s0.w, s1.w, s2.w, s3.w, t0.w, t1.w, t2.w, t3.w, P1.w, P2.w, P3.w, m3);

    g_masks4[q] = make_uchar4((unsigned char)m0, (unsigned char)m1,
                              (unsigned char)m2, (unsigned char)m3);
    int base = (b * 3) * 16384 + pq;
    g_p4[base]             = P1;
    g_p4[base + 16384]     = P2;
    g_p4[base + 2 * 16384] = P3;
}

// -------- kernel 2: transpose masks into column-packed bit planes + counts --------
__global__ void __launch_bounds__(256) k_pack() {
    int b = blockIdx.x >> 3;
    int w = blockIdx.x & 7;
    int j = threadIdx.x;

    const unsigned char* mk = ((const unsigned char*)g_masks4) + (size_t)b * HW + j;
    unsigned wd[6] = {0, 0, 0, 0, 0, 0};
    #pragma unroll 8
    for (int i2 = 0; i2 < 32; i2++) {
        unsigned m = mk[(w * 32 + i2) * WW];
        #pragma unroll
        for (int bit = 0; bit < 6; bit++)
            wd[bit] |= ((m >> bit) & 1u) << i2;
    }
    #pragma unroll
    for (int cc = 0; cc < 3; cc++) {
        int s = b * 3 + cc;
        g_bits[(0 * NSLICE + s) * 8 * WW + w * WW + j] = wd[cc];       // p-plane
        g_bits[(1 * NSLICE + s) * 8 * WW + w * WW + j] = wd[3 + cc];   // t-plane
    }

    __shared__ int scnt[6];
    if (threadIdx.x < 6) scnt[threadIdx.x] = 0;
    __syncthreads();
    #pragma unroll
    for (int bit = 0; bit < 6; bit++) {
        int tot = __reduce_add_sync(0xffffffffu, __popc(wd[bit]));
        if ((threadIdx.x & 31) == 0) atomicAdd(&scnt[bit], tot);
    }
    __syncthreads();
    if (threadIdx.x < 3)      atomicAdd(&g_cnt[b * 3 + threadIdx.x], scnt[threadIdx.x]);
    else if (threadIdx.x < 6) atomicAdd(&g_cnt[NSLICE + b * 3 + threadIdx.x - 3], scnt[threadIdx.x]);
}

// exact search: unconditional ±WIN window (independent LDS, clamped indices are
// over-estimates of valid candidates -> still exact), then rare break-loop tail
__device__ __forceinline__ int edt_search(const int* __restrict__ G, int j) {
    int best = G[j];
    #pragma unroll
    for (int d = 1; d <= WIN; d++) {
        int dd = d * d;
        int a = G[max(j - d, 0)] + dd;
        int b = G[min(j + d, WW - 1)] + dd;
        best = min(best, min(a, b));
    }
    if ((WIN + 1) * (WIN + 1) < best) {
        for (int d = WIN + 1; d < WW; d++) {
            int dd = d * d;
            if (dd >= best) break;
            int jm = j - d, jp = j + d;
            if (jm >= 0) best = min(best, G[jm] + dd);
            if (jp < WW) best = min(best, G[jp] + dd);
        }
    }
    return best;
}

// on-demand out-of-word fallbacks for one plane/column (early-break; usually 1 iter)
__device__ __forceinline__ void fallbacks(const unsigned* __restrict__ P, int j, int w0,
                                          int& fb0, int& fb1, int& la0, int& la1) {
    fb0 = BIG; fb1 = BIG;
    for (int w = w0 + 1; w < 8 && (fb0 == BIG || fb1 == BIG); w++) {
        unsigned ww = P[w * WW + j];
        if (fb0 == BIG && ~ww) fb0 = w * 32 + __ffs(~ww) - 1;
        if (fb1 == BIG &&  ww) fb1 = w * 32 + __ffs(ww) - 1;
    }
    la0 = -BIG; la1 = -BIG;
    for (int w = w0 - 1; w >= 0 && (la0 == -BIG || la1 == -BIG); w--) {
        unsigned ww = P[w * WW + j];
        if (la0 == -BIG && ~ww) la0 = w * 32 + 31 - __clz(~ww);
        if (la1 == -BIG &&  ww) la1 = w * 32 + 31 - __clz(ww);
    }
}

// per-row vertical distances from register word + precomputed fallbacks
__device__ __forceinline__ void vrow(unsigned cur, int br, int R,
                                     int fb0, int fb1, int la0, int la1,
                                     int& d0, int& d1) {
    unsigned hi = 0xFFFFFFFFu << br;
    unsigned lo = 0xFFFFFFFFu >> (31 - br);
    unsigned nc = ~cur;

    unsigned x0 = nc & hi;
    int dn0 = x0 ? (__ffs(x0) - 1 - br) : (fb0 - R);
    unsigned y0 = nc & lo;
    int up0 = y0 ? (br - (31 - __clz(y0))) : (R - la0);
    d0 = min(min(dn0, up0), CAP);

    unsigned x1 = cur & hi;
    int dn1 = x1 ? (__ffs(x1) - 1 - br) : (fb1 - R);
    unsigned y1 = cur & lo;
    int up1 = y1 ? (br - (31 - __clz(y1))) : (R - la1);
    d1 = min(min(dn1, up1), CAP);
}

// -------- kernel 3: fused vertical+horizontal EDT + loss + finalize --------
// block = (slice, 4-row band); grid = 24*64 = 1536
__global__ void __launch_bounds__(256) k_main(float* __restrict__ out) {
    int s    = blockIdx.x >> 6;    // slice 0..23
    int band = blockIdx.x & 63;    // 4-row band 0..63
    int j    = threadIdx.x;        // column
    int w0   = band >> 3;          // word holding all 4 rows
    int bb   = (band & 7) * 4;     // bit base within word

    const unsigned* Pp = g_bits + (size_t)(0 * NSLICE + s) * 8 * WW;
    const unsigned* Pt = g_bits + (size_t)(1 * NSLICE + s) * 8 * WW;

    unsigned curp = Pp[w0 * WW + j];
    unsigned curt = Pt[w0 * WW + j];
    int fb0p, fb1p, la0p, la1p, fb0t, fb1t, la0t, la1t;
    fallbacks(Pp, j, w0, fb0p, fb1p, la0p, la1p);
    fallbacks(Pt, j, w0, fb0t, fb1t, la0t, la1t);

    __shared__ int G[RPB][4][WW];
    #pragma unroll
    for (int r = 0; r < RPB; r++) {
        int br = bb + r;
        int R  = band * RPB + r;
        int d0, d1;
        vrow(curp, br, R, fb0p, fb1p, la0p, la1p, d0, d1);
        G[r][0][j] = d0 * d0;
        G[r][1][j] = d1 * d1;
        vrow(curt, br, R, fb0t, fb1t, la0t, la1t, d0, d1);
        G[r][2][j] = d0 * d0;
        G[r][3][j] = d1 * d1;
    }
    __syncthreads();               // ONE barrier per block

    int cp = g_cnt[s], ct = g_cnt[NSLICE + s];
    float vp = (cp > 0 && cp < HW) ? 1.0f : 0.0f;
    float vt = (ct > 0 && ct < HW) ? 1.0f : 0.0f;

    const float* prow = ((const float*)g_p4) + (size_t)s * HW + (size_t)band * RPB * WW + j;

    float acc = 0.0f;
    #pragma unroll
    for (int r = 0; r < RPB; r++) {
        int br = bb + r;
        int p_true = (curp >> br) & 1;
        int t_true = (curt >> br) & 1;
        int dp = edt_search(&G[r][p_true ? 0 : 1][0], j);
        int dt = edt_search(&G[r][t_true ? 2 : 3][0], j);
        float p   = prow[r * WW];
        float err = (p - (float)t_true) * (p - (float)t_true);
        acc += err * ((float)dp * vp + (float)dt * vt);
    }

    // block reduction -> double atomic (once per block)
    #pragma unroll
    for (int o = 16; o; o >>= 1) acc += __shfl_down_sync(0xffffffffu, acc, o);
    __shared__ float wsum[8];
    if ((threadIdx.x & 31) == 0) wsum[threadIdx.x >> 5] = acc;
    __syncthreads();
    if (threadIdx.x == 0) {
        float ssum = 0.0f;
        #pragma unroll
        for (int w = 0; w < 8; w++) ssum += wsum[w];
        atomicAdd(&g_acc, (double)ssum);
        __threadfence();
        int ticket = atomicAdd(&g_done, 1);
        if (ticket == NMAIN - 1) {             // last block finalizes
            double total = atomicAdd(&g_acc, 0.0);
            double mean  = total / (double)(NSLICE * HW);
            out[0] = (float)log(mean + 1.0);
        }
    }
}

extern "C" void kernel_launch(void* const* d_in, const int* in_sizes, int n_in,
                              void* d_out, int out_size) {
    const float4* S = (const float4*)d_in[0];   // preds_S (8,4,256,256)
    const float4* T = (const float4*)d_in[1];   // preds_T (8,4,256,256)
    (void)in_sizes; (void)n_in; (void)out_size; // target (d_in[2]) unused by reference

    k_prep<<<NPIX / 4 / 256, 256>>>(S, T);
    k_pack<<<64, 256>>>();
    k_main<<<NMAIN, 256>>>((float*)d_out);
}

// round 7
// speedup vs baseline: 1.4101x; 1.0264x over previous
#include <cuda_runtime.h>
#include <cuda_fp16.h>
#include <math.h>

#define HH 256
#define WW 256
#define HW 65536
#define NB 8
#define NSLICE 24      // NB * 3 kept channels
#define NPIX (NB*HW)   // 524288
#define CAP 512        // INF = H + W in reference
#define BIG (1<<20)
#define RPB 4          // rows per block in k_main
#define NMAIN (NSLICE * (HH / RPB))   // 1536 blocks
#define WIN 5          // unconditional search window

// -------- device scratch (no allocations allowed) --------
__device__ unsigned short g_masks2[NPIX / 2];    // per-pixel bytes: bits 0..2 mask_p cc, 3..5 mask_t cc
__device__ __half2        g_err2[NSLICE * HW / 2]; // (p - t)^2 per kept channel, fp16
__device__ unsigned       g_bits[2 * NSLICE * 8 * WW]; // column-packed bits [plane][slice][word][col]
__device__ int            g_cnt[2 * NSLICE];     // [0..23] p-counts, [24..47] t-counts
__device__ double         g_acc;
__device__ int            g_done;

// per-pixel softmax(4) + argmax(4) -> squared errors of ch 1..3 + 6 mask bits
__device__ __forceinline__ void pixel_work(float s0, float s1, float s2, float s3,
                                           float t0, float t1, float t2, float t3,
                                           float& e1o, float& e2o, float& e3o,
                                           unsigned& mk) {
    float m  = fmaxf(fmaxf(s0, s1), fmaxf(s2, s3));
    float e0 = __expf(s0 - m), e1 = __expf(s1 - m), e2 = __expf(s2 - m), e3 = __expf(s3 - m);
    float inv = 1.0f / (e0 + e1 + e2 + e3);
    float p1 = e1 * inv, p2 = e2 * inv, p3 = e3 * inv;

    int lab = 0; float best = t0;            // first-index-wins (matches jnp.argmax)
    if (t1 > best) { best = t1; lab = 1; }
    if (t2 > best) { best = t2; lab = 2; }
    if (t3 > best) { best = t3; lab = 3; }

    float g1 = (lab == 1) ? 1.0f : 0.0f;
    float g2 = (lab == 2) ? 1.0f : 0.0f;
    float g3 = (lab == 3) ? 1.0f : 0.0f;
    e1o = (p1 - g1) * (p1 - g1);
    e2o = (p2 - g2) * (p2 - g2);
    e3o = (p3 - g3) * (p3 - g3);

    mk = 0;
    if (p1 > 0.5f) mk |= 1u;
    if (p2 > 0.5f) mk |= 2u;
    if (p3 > 0.5f) mk |= 4u;
    mk |= ((unsigned)(g1) << 3) | ((unsigned)(g2) << 4) | ((unsigned)(g3) << 5);
}

// -------- kernel 1: softmax + argmax + masks + err (2 px/thread) + zero accumulators --------
__global__ void __launch_bounds__(256) k_prep(const float2* __restrict__ S2,
                                              const float2* __restrict__ T2) {
    if (blockIdx.x == 0) {                      // accumulators consumed only by LATER kernels
        if (threadIdx.x < 2 * NSLICE) g_cnt[threadIdx.x] = 0;
        if (threadIdx.x == 2 * NSLICE) { g_acc = 0.0; g_done = 0; }
    }

    int q  = blockIdx.x * 256 + threadIdx.x;   // pixel-pair index
    int b  = q >> 15;                          // 32768 pairs per image
    int pq = q & 32767;

    const float2* s = S2 + (size_t)b * 4 * 32768 + pq;
    float2 s0 = s[0], s1 = s[32768], s2 = s[2 * 32768], s3 = s[3 * 32768];
    const float2* t = T2 + (size_t)b * 4 * 32768 + pq;
    float2 t0 = t[0], t1 = t[32768], t2 = t[2 * 32768], t3 = t[3 * 32768];

    float a1, a2, a3, b1, b2, b3;
    unsigned m0, m1;
    pixel_work(s0.x, s1.x, s2.x, s3.x, t0.x, t1.x, t2.x, t3.x, a1, a2, a3, m0);
    pixel_work(s0.y, s1.y, s2.y, s3.y, t0.y, t1.y, t2.y, t3.y, b1, b2, b3, m1);

    g_masks2[q] = (unsigned short)(m0 | (m1 << 8));
    int base = (b * 3) * 32768 + pq;
    g_err2[base]             = __floats2half2_rn(a1, b1);
    g_err2[base + 32768]     = __floats2half2_rn(a2, b2);
    g_err2[base + 2 * 32768] = __floats2half2_rn(a3, b3);
}

// -------- kernel 2: transpose masks into column-packed bit planes + counts --------
__global__ void __launch_bounds__(256) k_pack() {
    int b = blockIdx.x >> 3;
    int w = blockIdx.x & 7;
    int j = threadIdx.x;

    const unsigned char* mk = ((const unsigned char*)g_masks2) + (size_t)b * HW + j;
    unsigned wd[6] = {0, 0, 0, 0, 0, 0};
    #pragma unroll 8
    for (int i2 = 0; i2 < 32; i2++) {
        unsigned m = mk[(w * 32 + i2) * WW];
        #pragma unroll
        for (int bit = 0; bit < 6; bit++)
            wd[bit] |= ((m >> bit) & 1u) << i2;
    }
    #pragma unroll
    for (int cc = 0; cc < 3; cc++) {
        int s = b * 3 + cc;
        g_bits[(0 * NSLICE + s) * 8 * WW + w * WW + j] = wd[cc];       // p-plane
        g_bits[(1 * NSLICE + s) * 8 * WW + w * WW + j] = wd[3 + cc];   // t-plane
    }

    __shared__ int scnt[6];
    if (threadIdx.x < 6) scnt[threadIdx.x] = 0;
    __syncthreads();
    #pragma unroll
    for (int bit = 0; bit < 6; bit++) {
        int tot = __reduce_add_sync(0xffffffffu, __popc(wd[bit]));
        if ((threadIdx.x & 31) == 0) atomicAdd(&scnt[bit], tot);
    }
    __syncthreads();
    if (threadIdx.x < 3)      atomicAdd(&g_cnt[b * 3 + threadIdx.x], scnt[threadIdx.x]);
    else if (threadIdx.x < 6) atomicAdd(&g_cnt[NSLICE + b * 3 + threadIdx.x - 3], scnt[threadIdx.x]);
}

// exact search: unconditional ±WIN window (independent LDS, clamped indices are
// over-estimates of valid candidates -> still exact), then rare break-loop tail
__device__ __forceinline__ int edt_search(const int* __restrict__ G, int j) {
    int best = G[j];
    #pragma unroll
    for (int d = 1; d <= WIN; d++) {
        int dd = d * d;
        int a = G[max(j - d, 0)] + dd;
        int b = G[min(j + d, WW - 1)] + dd;
        best = min(best, min(a, b));
    }
    if ((WIN + 1) * (WIN + 1) < best) {
        for (int d = WIN + 1; d < WW; d++) {
            int dd = d * d;
            if (dd >= best) break;
            int jm = j - d, jp = j + d;
            if (jm >= 0) best = min(best, G[jm] + dd);
            if (jp < WW) best = min(best, G[jp] + dd);
        }
    }
    return best;
}

// on-demand out-of-word fallbacks for one plane/column (early-break; usually 1 iter)
__device__ __forceinline__ void fallbacks(const unsigned* __restrict__ P, int j, int w0,
                                          int& fb0, int& fb1, int& la0, int& la1) {
    fb0 = BIG; fb1 = BIG;
    for (int w = w0 + 1; w < 8 && (fb0 == BIG || fb1 == BIG); w++) {
        unsigned ww = P[w * WW + j];
        if (fb0 == BIG && ~ww) fb0 = w * 32 + __ffs(~ww) - 1;
        if (fb1 == BIG &&  ww) fb1 = w * 32 + __ffs(ww) - 1;
    }
    la0 = -BIG; la1 = -BIG;
    for (int w = w0 - 1; w >= 0 && (la0 == -BIG || la1 == -BIG); w--) {
        unsigned ww = P[w * WW + j];
        if (la0 == -BIG && ~ww) la0 = w * 32 + 31 - __clz(~ww);
        if (la1 == -BIG &&  ww) la1 = w * 32 + 31 - __clz(ww);
    }
}

// per-row vertical distances from register word + precomputed fallbacks
__device__ __forceinline__ void vrow(unsigned cur, int br, int R,
                                     int fb0, int fb1, int la0, int la1,
                                     int& d0, int& d1) {
    unsigned hi = 0xFFFFFFFFu << br;
    unsigned lo = 0xFFFFFFFFu >> (31 - br);
    unsigned nc = ~cur;

    unsigned x0 = nc & hi;
    int dn0 = x0 ? (__ffs(x0) - 1 - br) : (fb0 - R);
    unsigned y0 = nc & lo;
    int up0 = y0 ? (br - (31 - __clz(y0))) : (R - la0);
    d0 = min(min(dn0, up0), CAP);

    unsigned x1 = cur & hi;
    int dn1 = x1 ? (__ffs(x1) - 1 - br) : (fb1 - R);
    unsigned y1 = cur & lo;
    int up1 = y1 ? (br - (31 - __clz(y1))) : (R - la1);
    d1 = min(min(dn1, up1), CAP);
}

// -------- kernel 3: fused vertical+horizontal EDT + loss + finalize --------
// block = (slice, 4-row band); grid = 24*64 = 1536
__global__ void __launch_bounds__(256) k_main(float* __restrict__ out) {
    int s    = blockIdx.x >> 6;    // slice 0..23
    int band = blockIdx.x & 63;    // 4-row band 0..63
    int j    = threadIdx.x;        // column
    int w0   = band >> 3;          // word holding all 4 rows
    int bb   = (band & 7) * 4;     // bit base within word

    const unsigned* Pp = g_bits + (size_t)(0 * NSLICE + s) * 8 * WW;
    const unsigned* Pt = g_bits + (size_t)(1 * NSLICE + s) * 8 * WW;

    unsigned curp = Pp[w0 * WW + j];
    unsigned curt = Pt[w0 * WW + j];
    int fb0p, fb1p, la0p, la1p, fb0t, fb1t, la0t, la1t;
    fallbacks(Pp, j, w0, fb0p, fb1p, la0p, la1p);
    fallbacks(Pt, j, w0, fb0t, fb1t, la0t, la1t);

    __shared__ int G[RPB][4][WW];
    #pragma unroll
    for (int r = 0; r < RPB; r++) {
        int br = bb + r;
        int R  = band * RPB + r;
        int d0, d1;
        vrow(curp, br, R, fb0p, fb1p, la0p, la1p, d0, d1);
        G[r][0][j] = d0 * d0;
        G[r][1][j] = d1 * d1;
        vrow(curt, br, R, fb0t, fb1t, la0t, la1t, d0, d1);
        G[r][2][j] = d0 * d0;
        G[r][3][j] = d1 * d1;
    }
    __syncthreads();               // ONE barrier per block

    int cp = g_cnt[s], ct = g_cnt[NSLICE + s];
    float vp = (cp > 0 && cp < HW) ? 1.0f : 0.0f;
    float vt = (ct > 0 && ct < HW) ? 1.0f : 0.0f;

    const __half* erow = ((const __half*)g_err2) + (size_t)s * HW + (size_t)band * RPB * WW + j;

    float acc = 0.0f;
    #pragma unroll
    for (int r = 0; r < RPB; r++) {
        int br = bb + r;
        int p_true = (curp >> br) & 1;
        int t_true = (curt >> br) & 1;
        int dp = edt_search(&G[r][p_true ? 0 : 1][0], j);
        int dt = edt_search(&G[r][t_true ? 2 : 3][0], j);
        float err = __half2float(erow[r * WW]);
        acc += err * ((float)dp * vp + (float)dt * vt);
    }

    // block reduction -> double atomic (once per block)
    #pragma unroll
    for (int o = 16; o; o >>= 1) acc += __shfl_down_sync(0xffffffffu, acc, o);
    __shared__ float wsum[8];
    if ((threadIdx.x & 31) == 0) wsum[threadIdx.x >> 5] = acc;
    __syncthreads();
    if (threadIdx.x == 0) {
        float ssum = 0.0f;
        #pragma unroll
        for (int w = 0; w < 8; w++) ssum += wsum[w];
        atomicAdd(&g_acc, (double)ssum);
        __threadfence();
        int ticket = atomicAdd(&g_done, 1);
        if (ticket == NMAIN - 1) {             // last block finalizes
            double total = atomicAdd(&g_acc, 0.0);
            double mean  = total / (double)(NSLICE * HW);
            out[0] = (float)log(mean + 1.0);
        }
    }
}

extern "C" void kernel_launch(void* const* d_in, const int* in_sizes, int n_in,
                              void* d_out, int out_size) {
    const float2* S = (const float2*)d_in[0];   // preds_S (8,4,256,256)
    const float2* T = (const float2*)d_in[1];   // preds_T (8,4,256,256)
    (void)in_sizes; (void)n_in; (void)out_size; // target (d_in[2]) unused by reference

    k_prep<<<NPIX / 2 / 256, 256>>>(S, T);
    k_pack<<<64, 256>>>();
    k_main<<<NMAIN, 256>>>((float*)d_out);
}